// round 4
// baseline (speedup 1.0000x reference)
#include <cuda_runtime.h>

#define SEQ 2048
#define HID 1024
#define NH  16
#define HD  64
#define VOCABN 50259

// ---- scratch (device globals; no allocation allowed) ----
__device__ float g_x[SEQ * HID];        // current residual stream x
__device__ float g_xpe[SEQ * HID];      // x + pos_emb
__device__ float g_qkv[SEQ * 3 * HID];  // [q | k | v] per row
__device__ float g_attn[SEQ * HID];     // attention output (pre-Wo)

// ============================================================
// Embedding: x = tok_emb[ids], xpe = x + pos_emb
// ============================================================
__global__ __launch_bounds__(256) void embed_kernel(
    const int* __restrict__ ids, const float* __restrict__ tok,
    const float* __restrict__ pos)
{
    int i = blockIdx.x * 256 + threadIdx.x;   // float4 index, SEQ*HID/4 total
    int s = i >> 8;                           // 256 float4 per row
    int c = i & 255;
    int t = ids[s];
    float4 v = reinterpret_cast<const float4*>(tok + (size_t)t * HID)[c];
    float4 p = reinterpret_cast<const float4*>(pos + (size_t)s * HID)[c];
    reinterpret_cast<float4*>(g_x + (size_t)s * HID)[c] = v;
    float4 w = make_float4(v.x + p.x, v.y + p.y, v.z + p.z, v.w + p.w);
    reinterpret_cast<float4*>(g_xpe + (size_t)s * HID)[c] = w;
}

// ============================================================
// SGEMM: C[m][n] = sum_k A[m][k] * B[n][k]   (A: [M,1024], B: [N,1024] row-major)
// MODE 0: C = acc                (ldc arbitrary, N bounded)
// MODE 1: C = resid + acc; xpe_out = C + pe   (ldc = HID)
// Tile 128x128x8, 256 threads, 8x8 per thread.
// ============================================================
template <int MODE>
__global__ __launch_bounds__(256) void sgemm_kernel(
    const float* __restrict__ A, const float* __restrict__ B,
    float* __restrict__ C, int N, int ldc,
    const float* __restrict__ resid, const float* __restrict__ pe,
    float* __restrict__ xpe_out)
{
    const int K = HID;
    __shared__ __align__(16) float As[8][128];
    __shared__ __align__(16) float Bs[8][128];

    int tid = threadIdx.x;
    int tx = tid & 15, ty = tid >> 4;
    int rowBase = blockIdx.y * 128;
    int colBase = blockIdx.x * 128;

    int lrow = tid >> 1;         // 0..127
    int lk4  = (tid & 1) * 4;    // 0 or 4

    float acc[8][8];
#pragma unroll
    for (int i = 0; i < 8; i++)
#pragma unroll
        for (int j = 0; j < 8; j++) acc[i][j] = 0.0f;

    const float* Aptr = A + (size_t)(rowBase + lrow) * K + lk4;
    int brow = colBase + lrow;
    bool bok = brow < N;
    const float* Bptr = B + (size_t)brow * K + lk4;

    for (int k0 = 0; k0 < K; k0 += 8) {
        float4 av = *reinterpret_cast<const float4*>(Aptr + k0);
        float4 bv = bok ? *reinterpret_cast<const float4*>(Bptr + k0)
                        : make_float4(0.f, 0.f, 0.f, 0.f);
        As[lk4 + 0][lrow] = av.x; As[lk4 + 1][lrow] = av.y;
        As[lk4 + 2][lrow] = av.z; As[lk4 + 3][lrow] = av.w;
        Bs[lk4 + 0][lrow] = bv.x; Bs[lk4 + 1][lrow] = bv.y;
        Bs[lk4 + 2][lrow] = bv.z; Bs[lk4 + 3][lrow] = bv.w;
        __syncthreads();
#pragma unroll
        for (int kk = 0; kk < 8; kk++) {
            float4 a0 = *reinterpret_cast<const float4*>(&As[kk][ty * 8]);
            float4 a1 = *reinterpret_cast<const float4*>(&As[kk][ty * 8 + 4]);
            float4 b0 = *reinterpret_cast<const float4*>(&Bs[kk][tx * 8]);
            float4 b1 = *reinterpret_cast<const float4*>(&Bs[kk][tx * 8 + 4]);
            float a[8] = {a0.x, a0.y, a0.z, a0.w, a1.x, a1.y, a1.z, a1.w};
            float b[8] = {b0.x, b0.y, b0.z, b0.w, b1.x, b1.y, b1.z, b1.w};
#pragma unroll
            for (int i = 0; i < 8; i++)
#pragma unroll
                for (int j = 0; j < 8; j++)
                    acc[i][j] = fmaf(a[i], b[j], acc[i][j]);
        }
        __syncthreads();
    }

#pragma unroll
    for (int i = 0; i < 8; i++) {
        int gr = rowBase + ty * 8 + i;
#pragma unroll
        for (int j = 0; j < 8; j++) {
            int gc = colBase + tx * 8 + j;
            if (gc < N) {
                if (MODE == 0) {
                    C[(size_t)gr * ldc + gc] = acc[i][j];
                } else {
                    float v = resid[(size_t)gr * HID + gc] + acc[i][j];
                    C[(size_t)gr * ldc + gc] = v;
                    xpe_out[(size_t)gr * HID + gc] = v + pe[(size_t)gr * HID + gc];
                }
            }
        }
    }
}

// ============================================================
// Flash attention (fp32), causal, hd=64.
// block = (qtile of 64 queries, head). 256 threads = 16x16, 4x4 per thread.
// qkv layout: row s -> [q(1024) | k(1024) | v(1024)], head h at col h*64.
// ============================================================
__global__ __launch_bounds__(256) void attn_kernel(
    const float* __restrict__ qkv, float* __restrict__ out)
{
    __shared__ __align__(16) float Qts[HD][64];   // [hd][qrow]
    __shared__ __align__(16) float KP[64][64];    // K^T [hd][krow], then P [qrow][krow]
    __shared__ __align__(16) float Vs[64][64];    // [krow][hd]

    int tid = threadIdx.x;
    int tx = tid & 15, ty = tid >> 4;
    int qt = blockIdx.x;     // 0..31
    int h  = blockIdx.y;     // 0..15

    // load Q tile, transposed into smem
#pragma unroll
    for (int it = 0; it < 4; it++) {
        int li = tid + it * 256;      // 0..1023
        int r  = li >> 4;             // query row in tile
        int c4 = (li & 15) * 4;       // hd col
        float4 v = *reinterpret_cast<const float4*>(
            qkv + (size_t)(qt * 64 + r) * (3 * HID) + h * HD + c4);
        Qts[c4 + 0][r] = v.x; Qts[c4 + 1][r] = v.y;
        Qts[c4 + 2][r] = v.z; Qts[c4 + 3][r] = v.w;
    }

    float m_i[4], l_i[4], o[4][4];
#pragma unroll
    for (int i = 0; i < 4; i++) {
        m_i[i] = -1e30f; l_i[i] = 0.0f;
#pragma unroll
        for (int j = 0; j < 4; j++) o[i][j] = 0.0f;
    }

    for (int kt = 0; kt <= qt; kt++) {
        __syncthreads();   // prev PV / Q-load done before overwriting KP, Vs
#pragma unroll
        for (int it = 0; it < 4; it++) {
            int li = tid + it * 256;
            int r  = li >> 4;             // key row in tile
            int c4 = (li & 15) * 4;
            const float* rowp = qkv + (size_t)(kt * 64 + r) * (3 * HID) + h * HD + c4;
            float4 kv = *reinterpret_cast<const float4*>(rowp + HID);
            KP[c4 + 0][r] = kv.x; KP[c4 + 1][r] = kv.y;
            KP[c4 + 2][r] = kv.z; KP[c4 + 3][r] = kv.w;
            float4 vv = *reinterpret_cast<const float4*>(rowp + 2 * HID);
            *reinterpret_cast<float4*>(&Vs[r][c4]) = vv;
        }
        __syncthreads();

        // S = Q K^T (rows ty*4.., cols tx*4..)
        float s[4][4];
#pragma unroll
        for (int i = 0; i < 4; i++)
#pragma unroll
            for (int j = 0; j < 4; j++) s[i][j] = 0.0f;
#pragma unroll
        for (int kk = 0; kk < HD; kk++) {
            float4 a = *reinterpret_cast<const float4*>(&Qts[kk][ty * 4]);
            float4 b = *reinterpret_cast<const float4*>(&KP[kk][tx * 4]);
            float av[4] = {a.x, a.y, a.z, a.w};
            float bv[4] = {b.x, b.y, b.z, b.w};
#pragma unroll
            for (int i = 0; i < 4; i++)
#pragma unroll
                for (int j = 0; j < 4; j++)
                    s[i][j] = fmaf(av[i], bv[j], s[i][j]);
        }

        // scale + causal mask (only diagonal tile)
#pragma unroll
        for (int i = 0; i < 4; i++)
#pragma unroll
            for (int j = 0; j < 4; j++) {
                s[i][j] *= 0.125f;   // 1/sqrt(64)
                if (kt == qt && (ty * 4 + i) < (tx * 4 + j)) s[i][j] = -1e30f;
            }

        // online softmax update
        float p[4][4];
#pragma unroll
        for (int i = 0; i < 4; i++) {
            float rm = fmaxf(fmaxf(s[i][0], s[i][1]), fmaxf(s[i][2], s[i][3]));
            rm = fmaxf(rm, __shfl_xor_sync(0xffffffffu, rm, 1));
            rm = fmaxf(rm, __shfl_xor_sync(0xffffffffu, rm, 2));
            rm = fmaxf(rm, __shfl_xor_sync(0xffffffffu, rm, 4));
            rm = fmaxf(rm, __shfl_xor_sync(0xffffffffu, rm, 8));
            float mn = fmaxf(m_i[i], rm);
            float alpha = __expf(m_i[i] - mn);
            float rs = 0.0f;
#pragma unroll
            for (int j = 0; j < 4; j++) { p[i][j] = __expf(s[i][j] - mn); rs += p[i][j]; }
            rs += __shfl_xor_sync(0xffffffffu, rs, 1);
            rs += __shfl_xor_sync(0xffffffffu, rs, 2);
            rs += __shfl_xor_sync(0xffffffffu, rs, 4);
            rs += __shfl_xor_sync(0xffffffffu, rs, 8);
            l_i[i] = l_i[i] * alpha + rs;
            m_i[i] = mn;
#pragma unroll
            for (int j = 0; j < 4; j++) o[i][j] *= alpha;
        }

        __syncthreads();   // everyone done reading K from KP
        // store P
#pragma unroll
        for (int i = 0; i < 4; i++)
#pragma unroll
            for (int j = 0; j < 4; j++) KP[ty * 4 + i][tx * 4 + j] = p[i][j];
        __syncthreads();

        // O += P V
#pragma unroll
        for (int kk = 0; kk < 64; kk++) {
            float a0 = KP[ty * 4 + 0][kk];
            float a1 = KP[ty * 4 + 1][kk];
            float a2 = KP[ty * 4 + 2][kk];
            float a3 = KP[ty * 4 + 3][kk];
            float4 b = *reinterpret_cast<const float4*>(&Vs[kk][tx * 4]);
            float bv[4] = {b.x, b.y, b.z, b.w};
#pragma unroll
            for (int j = 0; j < 4; j++) {
                o[0][j] = fmaf(a0, bv[j], o[0][j]);
                o[1][j] = fmaf(a1, bv[j], o[1][j]);
                o[2][j] = fmaf(a2, bv[j], o[2][j]);
                o[3][j] = fmaf(a3, bv[j], o[3][j]);
            }
        }
    }

    // finalize
#pragma unroll
    for (int i = 0; i < 4; i++) {
        float inv = 1.0f / l_i[i];
        int gq = qt * 64 + ty * 4 + i;
#pragma unroll
        for (int j = 0; j < 4; j++)
            out[(size_t)gq * HID + h * HD + tx * 4 + j] = o[i][j] * inv;
    }
}

// ============================================================
// launch
// ============================================================
extern "C" void kernel_launch(void* const* d_in, const int* in_sizes, int n_in,
                              void* d_out, int out_size)
{
    const int*   ids   = (const int*)d_in[0];
    const float* tok   = (const float*)d_in[1];
    const float* pos   = (const float*)d_in[2];
    const float* Wqkv0 = (const float*)d_in[3];
    const float* Wo0   = (const float*)d_in[4];
    const float* Wqkv1 = (const float*)d_in[5];
    const float* Wo1   = (const float*)d_in[6];
    float* out = (float*)d_out;

    float *x, *xpe, *qkvb, *attnb;
    cudaGetSymbolAddress((void**)&x,     g_x);
    cudaGetSymbolAddress((void**)&xpe,   g_xpe);
    cudaGetSymbolAddress((void**)&qkvb,  g_qkv);
    cudaGetSymbolAddress((void**)&attnb, g_attn);

    // embed: x, xpe
    embed_kernel<<<SEQ * HID / 4 / 256, 256>>>(ids, tok, pos);

    dim3 blk(256);
    dim3 grid_qk(2048 / 128, SEQ / 128);    // N=2048
    dim3 grid_h (1024 / 128, SEQ / 128);    // N=1024
    dim3 grid_lm((VOCABN + 127) / 128, SEQ / 128);
    dim3 grid_at(SEQ / 64, NH);

    // ---- layer 0 ----
    sgemm_kernel<0><<<grid_qk, blk>>>(xpe, Wqkv0, qkvb, 2048, 3 * HID,
                                      nullptr, nullptr, nullptr);
    sgemm_kernel<0><<<grid_h, blk>>>(x, Wqkv0 + (size_t)2048 * HID, qkvb + 2048,
                                     1024, 3 * HID, nullptr, nullptr, nullptr);
    attn_kernel<<<grid_at, blk>>>(qkvb, attnb);
    sgemm_kernel<1><<<grid_h, blk>>>(attnb, Wo0, x, 1024, HID, x, pos, xpe);

    // ---- layer 1 ----
    sgemm_kernel<0><<<grid_qk, blk>>>(xpe, Wqkv1, qkvb, 2048, 3 * HID,
                                      nullptr, nullptr, nullptr);
    sgemm_kernel<0><<<grid_h, blk>>>(x, Wqkv1 + (size_t)2048 * HID, qkvb + 2048,
                                     1024, 3 * HID, nullptr, nullptr, nullptr);
    attn_kernel<<<grid_at, blk>>>(qkvb, attnb);
    sgemm_kernel<1><<<grid_h, blk>>>(attnb, Wo1, x, 1024, HID, x, pos, xpe);

    // ---- LM head ----
    sgemm_kernel<0><<<grid_lm, blk>>>(x, tok, out, VOCABN, VOCABN,
                                      nullptr, nullptr, nullptr);
}

// round 12
// speedup vs baseline: 1.9539x; 1.9539x over previous
#include <cuda_runtime.h>
#include <cuda_bf16.h>
#include <cstdint>

#define SEQ 2048
#define HID 1024
#define NH  16
#define HD  64
#define VOCABN 50259

#define KTOT 3072          // split-bf16: K' = 3*1024
#define BM 128
#define BN 256
#define BK 32              // bf16 elems per K chunk (64 bytes)
#define NCH (KTOT / BK)    // 96
#define STAGES 4
#define ROWB 80            // padded smem row: 32 bf16 + 8 pad = 80 bytes (conflict-free)
#define A_BYTES (BM * ROWB)            // 10240
#define B_BYTES (BN * ROWB)            // 20480
#define STAGE_BYTES (A_BYTES + B_BYTES) // 30720
#define SMEM_BYTES (STAGES * STAGE_BYTES) // 122880

// ---- scratch (device globals; no allocation allowed) ----
__device__ float g_x[SEQ * HID];
__device__ float g_xpe[SEQ * HID];
__device__ float g_qkv[SEQ * 3 * HID];
__device__ float g_attn[SEQ * HID];
__device__ __align__(16) __nv_bfloat16 g_tok[(size_t)VOCABN * KTOT];   // B-style split
__device__ __align__(16) __nv_bfloat16 g_w[(size_t)3 * HID * KTOT];    // weight split (reused)
__device__ __align__(16) __nv_bfloat16 g_ap[(size_t)SEQ * KTOT];       // xpe split (A-style)
__device__ __align__(16) __nv_bfloat16 g_ax[(size_t)SEQ * KTOT];       // x split
__device__ __align__(16) __nv_bfloat16 g_aat[(size_t)SEQ * KTOT];      // attn-out split

// ============================================================
// helpers
// ============================================================
__device__ __forceinline__ uint32_t smem_to_u32(const void* p) {
    uint32_t a;
    asm("{ .reg .u64 t; cvta.to.shared.u64 t, %1; cvt.u32.u64 %0, t; }" : "=r"(a) : "l"(p));
    return a;
}
__device__ __forceinline__ void cp16(uint32_t dst, const void* src) {
    asm volatile("cp.async.cg.shared.global [%0], [%1], 16;" :: "r"(dst), "l"(src));
}
#define CP_COMMIT() asm volatile("cp.async.commit_group;" ::: "memory")
#define CP_WAIT2()  asm volatile("cp.async.wait_group %0;" :: "n"(STAGES - 2) : "memory")

__device__ __forceinline__ void ldsm4(uint32_t* r, uint32_t addr) {
    asm volatile("ldmatrix.sync.aligned.m8n8.x4.shared.b16 {%0,%1,%2,%3}, [%4];"
                 : "=r"(r[0]), "=r"(r[1]), "=r"(r[2]), "=r"(r[3]) : "r"(addr));
}
__device__ __forceinline__ void mma16816(float* c, const uint32_t* a, const uint32_t* b) {
    asm volatile(
        "mma.sync.aligned.m16n8k16.row.col.f32.bf16.bf16.f32 "
        "{%0,%1,%2,%3}, {%4,%5,%6,%7}, {%8,%9}, {%0,%1,%2,%3};"
        : "+f"(c[0]), "+f"(c[1]), "+f"(c[2]), "+f"(c[3])
        : "r"(a[0]), "r"(a[1]), "r"(a[2]), "r"(a[3]), "r"(b[0]), "r"(b[1]));
}

// ============================================================
// Embedding: x = tok_emb[ids], xpe = x + pos_emb
// ============================================================
__global__ __launch_bounds__(256) void embed_kernel(
    const int* __restrict__ ids, const float* __restrict__ tok,
    const float* __restrict__ pos)
{
    int i = blockIdx.x * 256 + threadIdx.x;
    int s = i >> 8;
    int c = i & 255;
    int t = ids[s];
    float4 v = reinterpret_cast<const float4*>(tok + (size_t)t * HID)[c];
    float4 p = reinterpret_cast<const float4*>(pos + (size_t)s * HID)[c];
    reinterpret_cast<float4*>(g_x + (size_t)s * HID)[c] = v;
    float4 w = make_float4(v.x + p.x, v.y + p.y, v.z + p.z, v.w + p.w);
    reinterpret_cast<float4*>(g_xpe + (size_t)s * HID)[c] = w;
}

// ============================================================
// Split conversion: fp32 [R,1024] -> bf16 [R,3072]
// A-style (LOSLOT=1): hi|lo|hi     B-style (LOSLOT=2): hi|hi|lo
// sum over K' of A'[k]*B'[k] = AhBh + AlBh + AhBl ~= A*B (err ~ AlBl ~ 4e-6)
// ============================================================
template <int LOSLOT>
__global__ __launch_bounds__(256) void conv_split(
    const float* __restrict__ src, __nv_bfloat16* __restrict__ dst, int total4)
{
    int i = blockIdx.x * 256 + threadIdx.x;
    if (i >= total4) return;
    int r = i >> 8;
    int k4 = (i & 255) * 4;
    float4 v = reinterpret_cast<const float4*>(src)[i];
    float vv[4] = {v.x, v.y, v.z, v.w};
    __nv_bfloat16 h[4], l[4];
#pragma unroll
    for (int j = 0; j < 4; j++) {
        h[j] = __float2bfloat16(vv[j]);
        l[j] = __float2bfloat16(vv[j] - __bfloat162float(h[j]));
    }
    __nv_bfloat162 hp0, hp1, lp0, lp1;
    hp0.x = h[0]; hp0.y = h[1]; hp1.x = h[2]; hp1.y = h[3];
    lp0.x = l[0]; lp0.y = l[1]; lp1.x = l[2]; lp1.y = l[3];
    __nv_bfloat16* row = dst + (size_t)r * KTOT;
#pragma unroll
    for (int slot = 0; slot < 3; slot++) {
        __nv_bfloat162* p = reinterpret_cast<__nv_bfloat162*>(row + slot * 1024 + k4);
        if (slot == LOSLOT) { p[0] = lp0; p[1] = lp1; }
        else                { p[0] = hp0; p[1] = hp1; }
    }
}

// ============================================================
// mma.sync bf16 GEMM: C[m][n] = sum_k A'[m][k] B'[n][k]   (K'=3072)
// Tile 128x256x32, 8 warps (warp tile 64x64), 4-stage cp.async pipeline.
// MODE 0: C = acc        MODE 1: C = resid + acc; xpe_out = C + pe
// ============================================================
__device__ __forceinline__ void load_chunk(
    uint32_t sA, uint32_t sB,
    const __nv_bfloat16* __restrict__ Ag, const __nv_bfloat16* __restrict__ Bg,
    int rowBase, int colBase, int Nb, int ch, int tid)
{
    const char* abase = (const char*)Ag + (size_t)ch * (BK * 2);
#pragma unroll
    for (int it = 0; it < 2; it++) {
        int q = tid + it * 256;          // 0..511
        int r = q >> 2, c = q & 3;
        cp16(sA + r * ROWB + c * 16,
             abase + (size_t)(rowBase + r) * (KTOT * 2) + c * 16);
    }
    const char* bbase = (const char*)Bg + (size_t)ch * (BK * 2);
#pragma unroll
    for (int it = 0; it < 4; it++) {
        int q = tid + it * 256;          // 0..1023
        int r = q >> 2, c = q & 3;
        int br = colBase + r;
        if (br > Nb - 1) br = Nb - 1;    // clamp; duplicated rows never stored
        cp16(sB + r * ROWB + c * 16,
             bbase + (size_t)br * (KTOT * 2) + c * 16);
    }
}

template <int MODE>
__global__ __launch_bounds__(256, 1) void mm_kernel(
    const __nv_bfloat16* __restrict__ Ag, const __nv_bfloat16* __restrict__ Bg,
    float* __restrict__ C, int Nb, int ldc,
    const float* __restrict__ resid, const float* __restrict__ pe,
    float* __restrict__ xpe_out)
{
    extern __shared__ __align__(128) char smem[];
    uint32_t sbase = smem_to_u32(smem);
    const int tid  = threadIdx.x;
    const int wid  = tid >> 5;
    const int lane = tid & 31;
    const int rowBase = blockIdx.y * BM;
    const int colBase = blockIdx.x * BN;
    const int wm = (wid & 1) * 64;    // warp M offset within tile
    const int wn = (wid >> 1) * 64;   // warp N offset within tile

    float acc[4][8][4];
#pragma unroll
    for (int mi = 0; mi < 4; mi++)
#pragma unroll
        for (int ni = 0; ni < 8; ni++)
#pragma unroll
            for (int e = 0; e < 4; e++) acc[mi][ni][e] = 0.0f;

    // prologue: stages 0..2
#pragma unroll
    for (int j = 0; j < STAGES - 1; j++) {
        uint32_t sA = sbase + j * STAGE_BYTES;
        load_chunk(sA, sA + A_BYTES, Ag, Bg, rowBase, colBase, Nb, j, tid);
        CP_COMMIT();
    }

    // precomputed ldmatrix lane offsets
    const int aRow = lane & 15;
    const int aCol = (lane >> 4) * 16;            // byte offset within k-half pair
    const int bRow = (lane & 7) + ((lane >> 4) << 3);
    const int bCol = ((lane >> 3) & 1) * 16;

    for (int j = 0; j < NCH; j++) {
        CP_WAIT2();
        __syncthreads();
        if (j + STAGES - 1 < NCH) {
            uint32_t sA2 = sbase + ((j + STAGES - 1) % STAGES) * STAGE_BYTES;
            load_chunk(sA2, sA2 + A_BYTES, Ag, Bg, rowBase, colBase, Nb,
                       j + STAGES - 1, tid);
        }
        CP_COMMIT();

        uint32_t sA = sbase + (j % STAGES) * STAGE_BYTES;
        uint32_t sB = sA + A_BYTES;
#pragma unroll
        for (int ks = 0; ks < 2; ks++) {
            uint32_t a[4][4];
#pragma unroll
            for (int mi = 0; mi < 4; mi++)
                ldsm4(a[mi], sA + (wm + mi * 16 + aRow) * ROWB + ks * 32 + aCol);
            uint32_t b[8][2];
#pragma unroll
            for (int nj = 0; nj < 4; nj++) {
                uint32_t r[4];
                ldsm4(r, sB + (wn + nj * 16 + bRow) * ROWB + ks * 32 + bCol);
                b[nj * 2 + 0][0] = r[0]; b[nj * 2 + 0][1] = r[1];
                b[nj * 2 + 1][0] = r[2]; b[nj * 2 + 1][1] = r[3];
            }
#pragma unroll
            for (int mi = 0; mi < 4; mi++)
#pragma unroll
                for (int ni = 0; ni < 8; ni++)
                    mma16816(acc[mi][ni], a[mi], b[ni]);
        }
    }

    // epilogue: c0,c1 -> row lane/4, cols 2*(lane%4)+{0,1}; c2,c3 -> row+8
    // NOTE: scalar stores only — ldc may be odd (VOCABN), so float2 would trap.
    const int erow = lane >> 2;
    const int ecol = (lane & 3) * 2;
#pragma unroll
    for (int mi = 0; mi < 4; mi++) {
#pragma unroll
        for (int half = 0; half < 2; half++) {
            int gr = rowBase + wm + mi * 16 + erow + half * 8;
            float* crow = C + (size_t)gr * ldc;
#pragma unroll
            for (int ni = 0; ni < 8; ni++) {
                int gc = colBase + wn + ni * 8 + ecol;
                float v0 = acc[mi][ni][half * 2 + 0];
                float v1 = acc[mi][ni][half * 2 + 1];
                if (MODE == 0) {
                    if (gc < Nb)     crow[gc]     = v0;
                    if (gc + 1 < Nb) crow[gc + 1] = v1;
                } else {
                    const float* rr = resid + (size_t)gr * HID;
                    const float* pp = pe + (size_t)gr * HID;
                    float* xx = xpe_out + (size_t)gr * HID;
                    float w0 = rr[gc] + v0;
                    float w1 = rr[gc + 1] + v1;
                    crow[gc] = w0; crow[gc + 1] = w1;
                    xx[gc] = w0 + pp[gc]; xx[gc + 1] = w1 + pp[gc + 1];
                }
            }
        }
    }
}

// ============================================================
// Flash attention (fp32), causal, hd=64 — unchanged.
// ============================================================
__global__ __launch_bounds__(256) void attn_kernel(
    const float* __restrict__ qkv, float* __restrict__ out)
{
    __shared__ __align__(16) float Qts[HD][64];
    __shared__ __align__(16) float KP[64][64];
    __shared__ __align__(16) float Vs[64][64];

    int tid = threadIdx.x;
    int tx = tid & 15, ty = tid >> 4;
    int qt = blockIdx.x;
    int h  = blockIdx.y;

#pragma unroll
    for (int it = 0; it < 4; it++) {
        int li = tid + it * 256;
        int r  = li >> 4;
        int c4 = (li & 15) * 4;
        float4 v = *reinterpret_cast<const float4*>(
            qkv + (size_t)(qt * 64 + r) * (3 * HID) + h * HD + c4);
        Qts[c4 + 0][r] = v.x; Qts[c4 + 1][r] = v.y;
        Qts[c4 + 2][r] = v.z; Qts[c4 + 3][r] = v.w;
    }

    float m_i[4], l_i[4], o[4][4];
#pragma unroll
    for (int i = 0; i < 4; i++) {
        m_i[i] = -1e30f; l_i[i] = 0.0f;
#pragma unroll
        for (int j = 0; j < 4; j++) o[i][j] = 0.0f;
    }

    for (int kt = 0; kt <= qt; kt++) {
        __syncthreads();
#pragma unroll
        for (int it = 0; it < 4; it++) {
            int li = tid + it * 256;
            int r  = li >> 4;
            int c4 = (li & 15) * 4;
            const float* rowp = qkv + (size_t)(kt * 64 + r) * (3 * HID) + h * HD + c4;
            float4 kv = *reinterpret_cast<const float4*>(rowp + HID);
            KP[c4 + 0][r] = kv.x; KP[c4 + 1][r] = kv.y;
            KP[c4 + 2][r] = kv.z; KP[c4 + 3][r] = kv.w;
            float4 vv = *reinterpret_cast<const float4*>(rowp + 2 * HID);
            *reinterpret_cast<float4*>(&Vs[r][c4]) = vv;
        }
        __syncthreads();

        float s[4][4];
#pragma unroll
        for (int i = 0; i < 4; i++)
#pragma unroll
            for (int j = 0; j < 4; j++) s[i][j] = 0.0f;
#pragma unroll
        for (int kk = 0; kk < HD; kk++) {
            float4 a = *reinterpret_cast<const float4*>(&Qts[kk][ty * 4]);
            float4 b = *reinterpret_cast<const float4*>(&KP[kk][tx * 4]);
            float av[4] = {a.x, a.y, a.z, a.w};
            float bv[4] = {b.x, b.y, b.z, b.w};
#pragma unroll
            for (int i = 0; i < 4; i++)
#pragma unroll
                for (int j = 0; j < 4; j++)
                    s[i][j] = fmaf(av[i], bv[j], s[i][j]);
        }

#pragma unroll
        for (int i = 0; i < 4; i++)
#pragma unroll
            for (int j = 0; j < 4; j++) {
                s[i][j] *= 0.125f;
                if (kt == qt && (ty * 4 + i) < (tx * 4 + j)) s[i][j] = -1e30f;
            }

        float p[4][4];
#pragma unroll
        for (int i = 0; i < 4; i++) {
            float rm = fmaxf(fmaxf(s[i][0], s[i][1]), fmaxf(s[i][2], s[i][3]));
            rm = fmaxf(rm, __shfl_xor_sync(0xffffffffu, rm, 1));
            rm = fmaxf(rm, __shfl_xor_sync(0xffffffffu, rm, 2));
            rm = fmaxf(rm, __shfl_xor_sync(0xffffffffu, rm, 4));
            rm = fmaxf(rm, __shfl_xor_sync(0xffffffffu, rm, 8));
            float mn = fmaxf(m_i[i], rm);
            float alpha = __expf(m_i[i] - mn);
            float rs = 0.0f;
#pragma unroll
            for (int j = 0; j < 4; j++) { p[i][j] = __expf(s[i][j] - mn); rs += p[i][j]; }
            rs += __shfl_xor_sync(0xffffffffu, rs, 1);
            rs += __shfl_xor_sync(0xffffffffu, rs, 2);
            rs += __shfl_xor_sync(0xffffffffu, rs, 4);
            rs += __shfl_xor_sync(0xffffffffu, rs, 8);
            l_i[i] = l_i[i] * alpha + rs;
            m_i[i] = mn;
#pragma unroll
            for (int j = 0; j < 4; j++) o[i][j] *= alpha;
        }

        __syncthreads();
#pragma unroll
        for (int i = 0; i < 4; i++)
#pragma unroll
            for (int j = 0; j < 4; j++) KP[ty * 4 + i][tx * 4 + j] = p[i][j];
        __syncthreads();

#pragma unroll
        for (int kk = 0; kk < 64; kk++) {
            float a0 = KP[ty * 4 + 0][kk];
            float a1 = KP[ty * 4 + 1][kk];
            float a2 = KP[ty * 4 + 2][kk];
            float a3 = KP[ty * 4 + 3][kk];
            float4 b = *reinterpret_cast<const float4*>(&Vs[kk][tx * 4]);
            float bv[4] = {b.x, b.y, b.z, b.w};
#pragma unroll
            for (int j = 0; j < 4; j++) {
                o[0][j] = fmaf(a0, bv[j], o[0][j]);
                o[1][j] = fmaf(a1, bv[j], o[1][j]);
                o[2][j] = fmaf(a2, bv[j], o[2][j]);
                o[3][j] = fmaf(a3, bv[j], o[3][j]);
            }
        }
    }

#pragma unroll
    for (int i = 0; i < 4; i++) {
        float inv = 1.0f / l_i[i];
        int gq = qt * 64 + ty * 4 + i;
#pragma unroll
        for (int j = 0; j < 4; j++)
            out[(size_t)gq * HID + h * HD + tx * 4 + j] = o[i][j] * inv;
    }
}

// ============================================================
// launch
// ============================================================
extern "C" void kernel_launch(void* const* d_in, const int* in_sizes, int n_in,
                              void* d_out, int out_size)
{
    const int*   ids   = (const int*)d_in[0];
    const float* tok   = (const float*)d_in[1];
    const float* pos   = (const float*)d_in[2];
    const float* Wqkv0 = (const float*)d_in[3];
    const float* Wo0   = (const float*)d_in[4];
    const float* Wqkv1 = (const float*)d_in[5];
    const float* Wo1   = (const float*)d_in[6];
    float* out = (float*)d_out;

    float *x, *xpe, *qkvb, *attnb;
    __nv_bfloat16 *tokb, *wb, *apb, *axb, *aatb;
    cudaGetSymbolAddress((void**)&x,     g_x);
    cudaGetSymbolAddress((void**)&xpe,   g_xpe);
    cudaGetSymbolAddress((void**)&qkvb,  g_qkv);
    cudaGetSymbolAddress((void**)&attnb, g_attn);
    cudaGetSymbolAddress((void**)&tokb,  g_tok);
    cudaGetSymbolAddress((void**)&wb,    g_w);
    cudaGetSymbolAddress((void**)&apb,   g_ap);
    cudaGetSymbolAddress((void**)&axb,   g_ax);
    cudaGetSymbolAddress((void**)&aatb,  g_aat);

    cudaFuncSetAttribute(mm_kernel<0>, cudaFuncAttributeMaxDynamicSharedMemorySize, SMEM_BYTES);
    cudaFuncSetAttribute(mm_kernel<1>, cudaFuncAttributeMaxDynamicSharedMemorySize, SMEM_BYTES);

    dim3 blk(256);
    const int SEQ4 = SEQ * 256;
    const int VOC4 = VOCABN * 256;

    // tok_emb B-style split (for LM head)
    conv_split<2><<<(VOC4 + 255) / 256, blk>>>(tok, tokb, VOC4);

    // embed
    embed_kernel<<<SEQ * HID / 4 / 256, blk>>>(ids, tok, pos);
    conv_split<1><<<SEQ4 / 256, blk>>>(xpe, apb, SEQ4);
    conv_split<1><<<SEQ4 / 256, blk>>>(x,   axb, SEQ4);

    dim3 grid_qk(2048 / BN, SEQ / BM);
    dim3 grid_h (1024 / BN, SEQ / BM);
    dim3 grid_lm((VOCABN + BN - 1) / BN, SEQ / BM);
    dim3 grid_at(SEQ / 64, NH);

    const float* Wq[2] = {Wqkv0, Wqkv1};
    const float* Wo[2] = {Wo0, Wo1};
    for (int l = 0; l < 2; l++) {
        conv_split<2><<<(3072 * 256) / 256, blk>>>(Wq[l], wb, 3072 * 256);
        // qk projection: A = xpe', B = Wqkv'[0:2048]
        mm_kernel<0><<<grid_qk, blk, SMEM_BYTES>>>(apb, wb, qkvb, 2048, 3 * HID,
                                                   nullptr, nullptr, nullptr);
        // v projection: A = x', B = Wqkv'[2048:3072]
        mm_kernel<0><<<grid_h, blk, SMEM_BYTES>>>(axb, wb + (size_t)2048 * KTOT,
                                                  qkvb + 2048, 1024, 3 * HID,
                                                  nullptr, nullptr, nullptr);
        attn_kernel<<<grid_at, blk>>>(qkvb, attnb);
        conv_split<1><<<SEQ4 / 256, blk>>>(attnb, aatb, SEQ4);
        conv_split<2><<<(1024 * 256) / 256, blk>>>(Wo[l], wb, 1024 * 256);
        // out proj + residual + pos-emb fusion
        mm_kernel<1><<<grid_h, blk, SMEM_BYTES>>>(aatb, wb, x, 1024, HID, x, pos, xpe);
        conv_split<1><<<SEQ4 / 256, blk>>>(xpe, apb, SEQ4);
        conv_split<1><<<SEQ4 / 256, blk>>>(x,   axb, SEQ4);
    }

    // LM head: A = x', B = tok'
    mm_kernel<0><<<grid_lm, blk, SMEM_BYTES>>>(axb, tokb, out, VOCABN, VOCABN,
                                               nullptr, nullptr, nullptr);
}